// round 2
// baseline (speedup 1.0000x reference)
#include <cuda_runtime.h>
#include <cuda_fp16.h>
#include <cstdint>

// ---------------- problem constants ----------------
#define B_ROWS 16384
#define D_FEAT 256
#define H_HID  64
#define O_OUT  256

// ---------------- device scratch (static, allocation-free) ----------------
__device__ __half g_u[(size_t)B_ROWS * D_FEAT];      // 8.4 MB, fp16 u
__device__ float  g_knot[D_FEAT * 64];
__device__ float  g_slope[D_FEAT * 65];
__device__ float  g_inter[D_FEAT * 65];

__device__ __forceinline__ uint32_t smem_u32(const void* p) {
    uint32_t a;
    asm("{ .reg .u64 t; cvta.to.shared.u64 t, %1; cvt.u32.u64 %0, t; }"
        : "=r"(a) : "l"(p));
    return a;
}

// =====================================================================
// Kernel 1: build piecewise-linear tables per feature d.
// u_d(x) = slope[k]*x + inter[k], where k = #knots < x.
// =====================================================================
__global__ void prep_pwl_kernel(const float* __restrict__ W1,
                                const float* __restrict__ b1,
                                const float* __restrict__ W2,
                                const float* __restrict__ b2)
{
    const int d = blockIdx.x;
    const int h = threadIdx.x;  // 64 threads

    const float w1 = W1[d * H_HID + h];
    const float bb = b1[d * H_HID + h];
    const float w2 = W2[d * H_HID + h];

    float t, ds, di;
    float base_s = 0.0f, base_i = 0.0f;
    if (w1 != 0.0f) {
        t  = -bb / w1;
        ds = fabsf(w1) * w2;                       // delta slope crossing t (L->R)
        di = (w1 > 0.0f) ? (w2 * bb) : (-w2 * bb); // delta intercept
        if (w1 < 0.0f) {                           // active at x = -inf
            base_s = w1 * w2;
            base_i = w2 * bb;
        }
    } else {
        t  = __int_as_float(0x7f800000);           // +inf: never crossed
        ds = 0.0f;
        di = 0.0f;
        base_i = w2 * fmaxf(bb, 0.0f);             // constant contribution
    }

    __shared__ float st[64];
    __shared__ float rs[64], ri[64];
    __shared__ float kt[64], kds[64], kdi[64];

    st[h] = t;
    rs[h] = base_s;
    ri[h] = base_i;
    __syncthreads();

    // reduce base slope/intercept
    for (int off = 32; off > 0; off >>= 1) {
        if (h < off) { rs[h] += rs[h + off]; ri[h] += ri[h + off]; }
        __syncthreads();
    }

    // rank sort (O(64) per thread)
    int rank = 0;
    #pragma unroll 8
    for (int j = 0; j < 64; j++) {
        float tj = st[j];
        rank += (tj < t) || (tj == t && j < h);
    }
    kt[rank]  = t;
    kds[rank] = ds;
    kdi[rank] = di;
    __syncthreads();

    if (h == 0) {
        float s  = rs[0];
        float ii = ri[0] + b2[d];
        g_slope[d * 65 + 0] = s;
        g_inter[d * 65 + 0] = ii;
        #pragma unroll 8
        for (int k = 0; k < 64; k++) {
            s  += kds[k];
            ii += kdi[k];
            g_slope[d * 65 + k + 1] = s;
            g_inter[d * 65 + k + 1] = ii;
        }
    }
    g_knot[d * 64 + h] = kt[h];
}

// =====================================================================
// Kernel 2: evaluate u[b,d] via binary search over the PWL tables.
// grid = (64 b-chunks of 256 rows, 8 d-groups of 32), 512 threads.
// =====================================================================
__global__ __launch_bounds__(512)
void eval_u_kernel(const float* __restrict__ x)
{
    __shared__ float skt[32 * 65];   // knots, stride 65 (bank spread)
    __shared__ float ssl[32 * 65];   // slopes
    __shared__ float sin_[32 * 65];  // intercepts

    const int d0 = blockIdx.y * 32;

    for (int i = threadIdx.x; i < 32 * 64; i += 512) {
        int dd = i >> 6, j = i & 63;
        skt[dd * 65 + j] = g_knot[(d0 + dd) * 64 + j];
    }
    for (int i = threadIdx.x; i < 32 * 65; i += 512) {
        int dd = i / 65, k = i % 65;
        ssl[dd * 65 + k]  = g_slope[(d0 + dd) * 65 + k];
        sin_[dd * 65 + k] = g_inter[(d0 + dd) * 65 + k];
    }
    __syncthreads();

    const int dd = threadIdx.x & 31;
    const int bl = threadIdx.x >> 5;       // 0..15
    const int d  = d0 + dd;
    const float* kt = &skt[dd * 65];
    const int bbase = blockIdx.x * 256;

    #pragma unroll 2
    for (int r = 0; r < 16; r++) {
        int b = bbase + r * 16 + bl;
        float xv = __ldg(&x[(size_t)b * D_FEAT + d]);
        int lo = 0;
        #pragma unroll
        for (int s = 64; s >= 1; s >>= 1) {
            if (lo + s <= 64) {
                float tv = kt[lo + s - 1];
                if (tv < xv) lo += s;
            }
        }
        float u = fmaf(ssl[dd * 65 + lo], xv, sin_[dd * 65 + lo]);
        g_u[(size_t)b * D_FEAT + d] = __float2half(u);
    }
}

// =====================================================================
// Kernel 3: GEMM out[16384,256] = u @ Wc^T + bc, via mma.sync (HMMA).
// CTA: M=128, N=256, K=256. 512 threads = 16 warps in 4(m) x 4(n),
// warp tile 32(m) x 64(n). A,B fp16 in padded smem (stride 264 halfs,
// 528B: mod 128 = 16 -> conflict-free ldmatrix).
// =====================================================================
#define K_PAD 264
#define A_SMEM_HALFS (128 * K_PAD)          // 33792
#define B_SMEM_HALFS (256 * K_PAD)          // 67584
#define GEMM_SMEM_BYTES ((A_SMEM_HALFS + B_SMEM_HALFS) * 2)  // 202752

__device__ __forceinline__ void ldsm_x4(uint32_t* r, uint32_t addr) {
    asm volatile("ldmatrix.sync.aligned.m8n8.x4.shared.b16 {%0,%1,%2,%3}, [%4];"
                 : "=r"(r[0]), "=r"(r[1]), "=r"(r[2]), "=r"(r[3]) : "r"(addr));
}
__device__ __forceinline__ void ldsm_x2(uint32_t* r, uint32_t addr) {
    asm volatile("ldmatrix.sync.aligned.m8n8.x2.shared.b16 {%0,%1}, [%2];"
                 : "=r"(r[0]), "=r"(r[1]) : "r"(addr));
}
__device__ __forceinline__ void mma_16816(float* c, const uint32_t* a,
                                          const uint32_t* b) {
    asm volatile(
        "mma.sync.aligned.m16n8k16.row.col.f32.f16.f16.f32 "
        "{%0,%1,%2,%3}, {%4,%5,%6,%7}, {%8,%9}, {%0,%1,%2,%3};"
        : "+f"(c[0]), "+f"(c[1]), "+f"(c[2]), "+f"(c[3])
        : "r"(a[0]), "r"(a[1]), "r"(a[2]), "r"(a[3]), "r"(b[0]), "r"(b[1]));
}

__global__ __launch_bounds__(512, 1)
void gemm_kernel(const float* __restrict__ Wc, const float* __restrict__ bc,
                 float* __restrict__ out)
{
    extern __shared__ __half smem[];
    __half* As = smem;                 // [128][K_PAD]
    __half* Bs = smem + A_SMEM_HALFS;  // [256][K_PAD]

    const int tid = threadIdx.x;
    const int wid = tid >> 5;
    const int lid = tid & 31;
    const int m0  = blockIdx.x * 128;

    // ---- fill A: u rows [m0, m0+128), 256 fp16 each (uint4 = 8 halfs) ----
    {
        const uint4* A = reinterpret_cast<const uint4*>(g_u + (size_t)m0 * D_FEAT);
        #pragma unroll
        for (int v = tid; v < 128 * 32; v += 512) {
            int m = v >> 5, k8 = (v & 31);
            uint4 val = A[m * 32 + k8];
            *reinterpret_cast<uint4*>(&As[m * K_PAD + k8 * 8]) = val;
        }
    }
    // ---- fill B: Wc [256][256] fp32 -> fp16 (float4 -> 4 halfs) ----
    {
        const float4* W = reinterpret_cast<const float4*>(Wc);
        #pragma unroll
        for (int v = tid; v < 256 * 64; v += 512) {
            int n = v >> 6, k4 = (v & 63);
            float4 f = W[n * 64 + k4];
            __half2 h0 = __float22half2_rn(make_float2(f.x, f.y));
            __half2 h1 = __float22half2_rn(make_float2(f.z, f.w));
            uint2 pk;
            pk.x = *reinterpret_cast<uint32_t*>(&h0);
            pk.y = *reinterpret_cast<uint32_t*>(&h1);
            *reinterpret_cast<uint2*>(&Bs[n * K_PAD + k4 * 4]) = pk;
        }
    }
    __syncthreads();

    const int warp_m = wid >> 2;   // 0..3
    const int warp_n = wid & 3;    // 0..3

    const uint32_t as_base = smem_u32(As);
    const uint32_t bs_base = smem_u32(Bs);

    // per-lane ldmatrix address components
    // A (.x4): row = warp_m*32 + tm*16 + (lid&15), col = k0 + ((lid>>4)<<3)
    const int a_row = warp_m * 32 + (lid & 15);
    const uint32_t a_lane = as_base
        + (uint32_t)(a_row * K_PAD + ((lid >> 4) << 3)) * 2u;
    // B (.x2): row(n) = warp_n*64 + tn*8 + (lid&7), col = k0 + ((lid>>3)&1)<<3
    const int b_row = warp_n * 64 + (lid & 7);
    const uint32_t b_lane = bs_base
        + (uint32_t)(b_row * K_PAD + (((lid >> 3) & 1) << 3)) * 2u;

    float acc[2][8][4];
    #pragma unroll
    for (int i = 0; i < 2; i++)
        #pragma unroll
        for (int j = 0; j < 8; j++)
            #pragma unroll
            for (int q = 0; q < 4; q++) acc[i][j][q] = 0.0f;

    #pragma unroll 4
    for (int ks = 0; ks < 16; ks++) {
        const uint32_t kb = (uint32_t)(ks * 16 * 2);  // byte advance along K
        uint32_t afr[2][4];
        #pragma unroll
        for (int tm = 0; tm < 2; tm++)
            ldsm_x4(afr[tm], a_lane + (uint32_t)(tm * 16 * K_PAD * 2) + kb);
        uint32_t bfr[8][2];
        #pragma unroll
        for (int tn = 0; tn < 8; tn++)
            ldsm_x2(bfr[tn], b_lane + (uint32_t)(tn * 8 * K_PAD * 2) + kb);
        #pragma unroll
        for (int tm = 0; tm < 2; tm++)
            #pragma unroll
            for (int tn = 0; tn < 8; tn++)
                mma_16816(acc[tm][tn], afr[tm], bfr[tn]);
    }

    // ---- epilogue: add bc, write fp32 ----
    const int qr = lid >> 2;            // 0..7
    const int qc = (lid & 3) * 2;       // 0,2,4,6
    #pragma unroll
    for (int tn = 0; tn < 8; tn++) {
        const int cb = warp_n * 64 + tn * 8 + qc;
        const float2 bcv = *reinterpret_cast<const float2*>(bc + cb);
        #pragma unroll
        for (int tm = 0; tm < 2; tm++) {
            const int r = m0 + warp_m * 32 + tm * 16 + qr;
            float2 v0, v1;
            v0.x = acc[tm][tn][0] + bcv.x;
            v0.y = acc[tm][tn][1] + bcv.y;
            v1.x = acc[tm][tn][2] + bcv.x;
            v1.y = acc[tm][tn][3] + bcv.y;
            *reinterpret_cast<float2*>(out + (size_t)r * O_OUT + cb) = v0;
            *reinterpret_cast<float2*>(out + (size_t)(r + 8) * O_OUT + cb) = v1;
        }
    }
}

// =====================================================================
// launch
// =====================================================================
extern "C" void kernel_launch(void* const* d_in, const int* in_sizes, int n_in,
                              void* d_out, int out_size)
{
    const float* x  = (const float*)d_in[0];
    const float* W1 = (const float*)d_in[1];
    const float* b1 = (const float*)d_in[2];
    const float* W2 = (const float*)d_in[3];
    const float* b2 = (const float*)d_in[4];
    const float* Wc = (const float*)d_in[5];
    const float* bc = (const float*)d_in[6];
    float* out = (float*)d_out;

    prep_pwl_kernel<<<D_FEAT, H_HID>>>(W1, b1, W2, b2);
    eval_u_kernel<<<dim3(B_ROWS / 256, D_FEAT / 32), 512>>>(x);

    static bool attr_set = false;
    if (!attr_set) {
        cudaFuncSetAttribute(gemm_kernel,
                             cudaFuncAttributeMaxDynamicSharedMemorySize,
                             GEMM_SMEM_BYTES);
        attr_set = true;
    }
    gemm_kernel<<<B_ROWS / 128, 512, GEMM_SMEM_BYTES>>>(Wc, bc, out);
}

// round 3
// speedup vs baseline: 1.0412x; 1.0412x over previous
#include <cuda_runtime.h>
#include <cuda_fp16.h>
#include <cstdint>

// ---------------- problem constants ----------------
#define B_ROWS 16384
#define D_FEAT 256
#define H_HID  64
#define O_OUT  256

// ---------------- device scratch (static, allocation-free) ----------------
__device__ __half g_u[(size_t)B_ROWS * D_FEAT];      // 8.4 MB, fp16 u
__device__ __half g_wc[(size_t)O_OUT * D_FEAT];      // Wc fp16
__device__ float  g_knot[D_FEAT * 64];
__device__ float  g_slope[D_FEAT * 65];
__device__ float  g_inter[D_FEAT * 65];

__device__ __forceinline__ uint32_t smem_u32(const void* p) {
    uint32_t a;
    asm("{ .reg .u64 t; cvta.to.shared.u64 t, %1; cvt.u32.u64 %0, t; }"
        : "=r"(a) : "l"(p));
    return a;
}

// =====================================================================
// Kernel 1: PWL table build (blocks 0..63: 4 warps, warp-per-feature)
//           + Wc fp32->fp16 convert (blocks 64..127).
// u_d(x) = slope[k]*x + inter[k], k = #knots < x.
// =====================================================================
__global__ __launch_bounds__(128)
void prep_kernel(const float* __restrict__ W1,
                 const float* __restrict__ b1,
                 const float* __restrict__ W2,
                 const float* __restrict__ b2,
                 const float* __restrict__ Wc)
{
    const int bid = blockIdx.x;

    if (bid >= 64) {
        // ---- Wc convert: 16384 float4 over 64 blocks x 128 threads ----
        const float4* W4 = reinterpret_cast<const float4*>(Wc);
        int base = (bid - 64) * 256 + threadIdx.x;  // float4 index
        #pragma unroll
        for (int i = 0; i < 2; i++) {
            int idx = base + i * 128;
            float4 f = W4[idx];
            __half2 h0 = __float22half2_rn(make_float2(f.x, f.y));
            __half2 h1 = __float22half2_rn(make_float2(f.z, f.w));
            uint2 pk;
            pk.x = *reinterpret_cast<uint32_t*>(&h0);
            pk.y = *reinterpret_cast<uint32_t*>(&h1);
            *reinterpret_cast<uint2*>(&g_wc[idx * 4]) = pk;
        }
        return;
    }

    const int w    = threadIdx.x >> 5;          // warp in block: 0..3
    const int lane = threadIdx.x & 31;
    const int d    = bid * 4 + w;

    __shared__ float s_t[4][64], s_ds[4][64], s_di[4][64];
    __shared__ float s_kt[4][64], s_kds[4][64], s_kdi[4][64];

    float t[2], ds[2], di[2];
    float bs = 0.0f, bi = 0.0f;
    #pragma unroll
    for (int i = 0; i < 2; i++) {
        const int h  = lane + i * 32;
        const float w1 = W1[d * H_HID + h];
        const float bb = b1[d * H_HID + h];
        const float w2 = W2[d * H_HID + h];
        if (w1 != 0.0f) {
            t[i]  = -bb / w1;
            ds[i] = fabsf(w1) * w2;
            di[i] = (w1 > 0.0f) ? (w2 * bb) : (-w2 * bb);
            if (w1 < 0.0f) { bs += w1 * w2; bi += w2 * bb; }
        } else {
            t[i]  = __int_as_float(0x7f800000);  // +inf
            ds[i] = 0.0f;
            di[i] = 0.0f;
            bi   += w2 * fmaxf(bb, 0.0f);
        }
        s_t[w][h]  = t[i];
        s_ds[w][h] = ds[i];
        s_di[w][h] = di[i];
    }

    // warp-reduce base slope/intercept (all lanes end with total)
    #pragma unroll
    for (int off = 16; off >= 1; off >>= 1) {
        bs += __shfl_xor_sync(0xffffffffu, bs, off);
        bi += __shfl_xor_sync(0xffffffffu, bi, off);
    }
    bi += b2[d];

    __syncwarp();
    // rank sort: 2 items per lane vs all 64
    int r0 = 0, r1 = 0;
    const float t0 = t[0], t1 = t[1];
    #pragma unroll 16
    for (int j = 0; j < 64; j++) {
        float tj = s_t[w][j];
        r0 += (tj < t0) || (tj == t0 && j < lane);
        r1 += (tj < t1) || (tj == t1 && j < lane + 32);
    }
    s_kt[w][r0]  = t0;  s_kds[w][r0] = ds[0]; s_kdi[w][r0] = di[0];
    s_kt[w][r1]  = t1;  s_kds[w][r1] = ds[1]; s_kdi[w][r1] = di[1];
    __syncwarp();

    // prefix scan over sorted deltas: lane holds positions 2l, 2l+1
    const float v0s = s_kds[w][2 * lane],     v1s = s_kds[w][2 * lane + 1];
    const float v0i = s_kdi[w][2 * lane],     v1i = s_kdi[w][2 * lane + 1];
    float incs = v0s + v1s, inci = v0i + v1i;
    const float ps = incs, pi = inci;
    #pragma unroll
    for (int off = 1; off < 32; off <<= 1) {
        float as_ = __shfl_up_sync(0xffffffffu, incs, off);
        float ai_ = __shfl_up_sync(0xffffffffu, inci, off);
        if (lane >= off) { incs += as_; inci += ai_; }
    }
    const float exs = incs - ps, exi = inci - pi;

    if (lane == 0) {
        g_slope[d * 65] = bs;
        g_inter[d * 65] = bi;
    }
    g_slope[d * 65 + 2 * lane + 1] = bs + exs + v0s;
    g_inter[d * 65 + 2 * lane + 1] = bi + exi + v0i;
    g_slope[d * 65 + 2 * lane + 2] = bs + incs;
    g_inter[d * 65 + 2 * lane + 2] = bi + inci;
    g_knot[d * 64 + 2 * lane]     = s_kt[w][2 * lane];
    g_knot[d * 64 + 2 * lane + 1] = s_kt[w][2 * lane + 1];
}

// =====================================================================
// Kernel 2: evaluate u[b,d] via binary search over the PWL tables.
// grid = (64 b-chunks of 256 rows, 8 d-groups of 32), 512 threads.
// =====================================================================
__global__ __launch_bounds__(512)
void eval_u_kernel(const float* __restrict__ x)
{
    __shared__ float skt[32 * 65];   // knots, stride 65 (bank spread)
    __shared__ float ssl[32 * 65];   // slopes
    __shared__ float sin_[32 * 65];  // intercepts

    const int d0 = blockIdx.y * 32;

    for (int i = threadIdx.x; i < 32 * 64; i += 512) {
        int dd = i >> 6, j = i & 63;
        skt[dd * 65 + j] = g_knot[(d0 + dd) * 64 + j];
    }
    for (int i = threadIdx.x; i < 32 * 65; i += 512) {
        int dd = i / 65, k = i % 65;
        ssl[dd * 65 + k]  = g_slope[(d0 + dd) * 65 + k];
        sin_[dd * 65 + k] = g_inter[(d0 + dd) * 65 + k];
    }
    __syncthreads();

    const int dd = threadIdx.x & 31;
    const int bl = threadIdx.x >> 5;       // 0..15
    const int d  = d0 + dd;
    const float* kt = &skt[dd * 65];
    const int bbase = blockIdx.x * 256;

    #pragma unroll 4
    for (int r = 0; r < 16; r++) {
        int b = bbase + r * 16 + bl;
        float xv = __ldg(&x[(size_t)b * D_FEAT + d]);
        int lo = 0;
        #pragma unroll
        for (int s = 64; s >= 1; s >>= 1) {
            if (lo + s <= 64) {
                float tv = kt[lo + s - 1];
                if (tv < xv) lo += s;
            }
        }
        float u = fmaf(ssl[dd * 65 + lo], xv, sin_[dd * 65 + lo]);
        g_u[(size_t)b * D_FEAT + d] = __float2half(u);
    }
}

// =====================================================================
// Kernel 3: GEMM out = u @ Wc^T + bc via mma.sync, cp.async pipelined.
// CTA: M=128, N=256, K=256 in 4 chunks of 64, double-buffered.
// 512 threads = 16 warps (4m x 4n), warp tile 32x64.
// Smem rows padded to 72 halfs (144B, mod128=16 -> conflict-free ldsm).
// =====================================================================
#define CH      64
#define CH_PAD  72
#define A_ST_H  (128 * CH_PAD)   // 9216 halfs / stage
#define B_ST_H  (256 * CH_PAD)   // 18432 halfs / stage
#define GEMM_SMEM_BYTES ((A_ST_H + B_ST_H) * 2 * 2)   // 110592

__device__ __forceinline__ void cp16(uint32_t dst, const void* src) {
    asm volatile("cp.async.cg.shared.global [%0], [%1], 16;"
                 :: "r"(dst), "l"(src));
}
#define CP_COMMIT() asm volatile("cp.async.commit_group;" ::: "memory")
#define CP_WAIT(n)  asm volatile("cp.async.wait_group %0;" :: "n"(n) : "memory")

__device__ __forceinline__ void ldsm_x4(uint32_t* r, uint32_t addr) {
    asm volatile("ldmatrix.sync.aligned.m8n8.x4.shared.b16 {%0,%1,%2,%3}, [%4];"
                 : "=r"(r[0]), "=r"(r[1]), "=r"(r[2]), "=r"(r[3]) : "r"(addr));
}
__device__ __forceinline__ void ldsm_x2(uint32_t* r, uint32_t addr) {
    asm volatile("ldmatrix.sync.aligned.m8n8.x2.shared.b16 {%0,%1}, [%2];"
                 : "=r"(r[0]), "=r"(r[1]) : "r"(addr));
}
__device__ __forceinline__ void mma_16816(float* c, const uint32_t* a,
                                          const uint32_t* b) {
    asm volatile(
        "mma.sync.aligned.m16n8k16.row.col.f32.f16.f16.f32 "
        "{%0,%1,%2,%3}, {%4,%5,%6,%7}, {%8,%9}, {%0,%1,%2,%3};"
        : "+f"(c[0]), "+f"(c[1]), "+f"(c[2]), "+f"(c[3])
        : "r"(a[0]), "r"(a[1]), "r"(a[2]), "r"(a[3]), "r"(b[0]), "r"(b[1]));
}

struct GemmCtx {
    uint32_t as_u32, bs_u32;
    const __half* Asrc;   // g_u + m0*256
    int tid;
};

__device__ __forceinline__ void issue_chunk(const GemmCtx& g, int c, int st) {
    // A: 128 rows x 64 halfs = 1024 x16B; 512 threads -> 2 each
    #pragma unroll
    for (int i = 0; i < 2; i++) {
        int idx = g.tid + i * 512;
        int row = idx >> 3, k8 = idx & 7;
        cp16(g.as_u32 + (uint32_t)((st * A_ST_H + row * CH_PAD + k8 * 8) * 2),
             g.Asrc + row * D_FEAT + c * CH + k8 * 8);
    }
    // B: 256 rows x 64 halfs = 2048 x16B; 4 each
    #pragma unroll
    for (int i = 0; i < 4; i++) {
        int idx = g.tid + i * 512;
        int row = idx >> 3, k8 = idx & 7;
        cp16(g.bs_u32 + (uint32_t)((st * B_ST_H + row * CH_PAD + k8 * 8) * 2),
             g_wc + row * D_FEAT + c * CH + k8 * 8);
    }
}

__global__ __launch_bounds__(512, 1)
void gemm_kernel(const float* __restrict__ bc, float* __restrict__ out)
{
    extern __shared__ __half smem[];
    __half* As = smem;                    // [2][128][CH_PAD]
    __half* Bs = smem + 2 * A_ST_H;       // [2][256][CH_PAD]

    const int tid = threadIdx.x;
    const int wid = tid >> 5;
    const int lid = tid & 31;
    const int m0  = blockIdx.x * 128;

    GemmCtx g;
    g.as_u32 = smem_u32(As);
    g.bs_u32 = smem_u32(Bs);
    g.Asrc   = g_u + (size_t)m0 * D_FEAT;
    g.tid    = tid;

    issue_chunk(g, 0, 0); CP_COMMIT();
    issue_chunk(g, 1, 1); CP_COMMIT();

    const int warp_m = wid >> 2;   // 0..3
    const int warp_n = wid & 3;    // 0..3

    // per-lane ldmatrix bases (stage 0)
    const int a_row = warp_m * 32 + (lid & 15);
    const uint32_t a_lane = g.as_u32
        + (uint32_t)((a_row * CH_PAD + ((lid >> 4) << 3)) * 2);
    const int b_row = warp_n * 64 + (lid & 7);
    const uint32_t b_lane = g.bs_u32
        + (uint32_t)((b_row * CH_PAD + (((lid >> 3) & 1) << 3)) * 2);

    float acc[2][8][4];
    #pragma unroll
    for (int i = 0; i < 2; i++)
        #pragma unroll
        for (int j = 0; j < 8; j++)
            #pragma unroll
            for (int q = 0; q < 4; q++) acc[i][j][q] = 0.0f;

    #pragma unroll
    for (int c = 0; c < 4; c++) {
        if (c < 3) { CP_WAIT(1); } else { CP_WAIT(0); }
        __syncthreads();

        const int st = c & 1;
        const uint32_t a_st = a_lane + (uint32_t)(st * A_ST_H * 2);
        const uint32_t b_st = b_lane + (uint32_t)(st * B_ST_H * 2);

        #pragma unroll
        for (int ks = 0; ks < 4; ks++) {            // K16 steps in chunk
            const uint32_t kb = (uint32_t)(ks * 32); // 16 halfs = 32B
            uint32_t afr[2][4];
            #pragma unroll
            for (int tm = 0; tm < 2; tm++)
                ldsm_x4(afr[tm], a_st + (uint32_t)(tm * 16 * CH_PAD * 2) + kb);
            uint32_t bfr[8][2];
            #pragma unroll
            for (int tn = 0; tn < 8; tn++)
                ldsm_x2(bfr[tn], b_st + (uint32_t)(tn * 8 * CH_PAD * 2) + kb);
            #pragma unroll
            for (int tm = 0; tm < 2; tm++)
                #pragma unroll
                for (int tn = 0; tn < 8; tn++)
                    mma_16816(acc[tm][tn], afr[tm], bfr[tn]);
        }

        __syncthreads();
        if (c < 2) { issue_chunk(g, c + 2, st); CP_COMMIT(); }
    }

    // ---- epilogue: add bc, write fp32 ----
    const int qr = lid >> 2;            // 0..7
    const int qc = (lid & 3) * 2;       // 0,2,4,6
    #pragma unroll
    for (int tn = 0; tn < 8; tn++) {
        const int cb = warp_n * 64 + tn * 8 + qc;
        const float2 bcv = *reinterpret_cast<const float2*>(bc + cb);
        #pragma unroll
        for (int tm = 0; tm < 2; tm++) {
            const int r = m0 + warp_m * 32 + tm * 16 + qr;
            float2 v0, v1;
            v0.x = acc[tm][tn][0] + bcv.x;
            v0.y = acc[tm][tn][1] + bcv.y;
            v1.x = acc[tm][tn][2] + bcv.x;
            v1.y = acc[tm][tn][3] + bcv.y;
            *reinterpret_cast<float2*>(out + (size_t)r * O_OUT + cb) = v0;
            *reinterpret_cast<float2*>(out + (size_t)(r + 8) * O_OUT + cb) = v1;
        }
    }
}

// =====================================================================
// launch
// =====================================================================
extern "C" void kernel_launch(void* const* d_in, const int* in_sizes, int n_in,
                              void* d_out, int out_size)
{
    const float* x  = (const float*)d_in[0];
    const float* W1 = (const float*)d_in[1];
    const float* b1 = (const float*)d_in[2];
    const float* W2 = (const float*)d_in[3];
    const float* b2 = (const float*)d_in[4];
    const float* Wc = (const float*)d_in[5];
    const float* bc = (const float*)d_in[6];
    float* out = (float*)d_out;

    prep_kernel<<<128, 128>>>(W1, b1, W2, b2, Wc);
    eval_u_kernel<<<dim3(B_ROWS / 256, D_FEAT / 32), 512>>>(x);
    gemm_kernel<<<B_ROWS / 128, 512, GEMM_SMEM_BYTES>>>(bc, out);
}

// set smem limit once at load time (host-side, not a device allocation)
namespace {
struct GemmAttrInit {
    GemmAttrInit() {
        cudaFuncSetAttribute(gemm_kernel,
                             cudaFuncAttributeMaxDynamicSharedMemorySize,
                             GEMM_SMEM_BYTES);
    }
} g_attr_init;
}